// round 1
// baseline (speedup 1.0000x reference)
#include <cuda_runtime.h>
#include <stdint.h>

// SparseLinear: out[n,64] = segment_sum(value * W[col,:], rows) + bias
// Strategy: counting-sort COO by row (histogram + scan + scatter), then
// warp-per-row register-accumulated gather SpMM. No output atomics.

#define OUTF 64
#define N_MAX 100000
#define NNZ_MAX 4000000
#define CHUNK 1024
#define MAXBLK 256   // max scan chunks (100000/1024 = 98)

__device__ int    g_counts[N_MAX];
__device__ int    g_offsets[N_MAX];
__device__ int    g_cursor[N_MAX];
__device__ int    g_blocksums[MAXBLK];
__device__ int    g_blockoff[MAXBLK];
__device__ float2 g_pairs[NNZ_MAX];   // .x = col bits (int), .y = value

// ---------------- Pass 1: zero counts ----------------
__global__ void k_zero(int n) {
    int i = blockIdx.x * blockDim.x + threadIdx.x;
    if (i < n) g_counts[i] = 0;
}

// ---------------- Pass 2: histogram rows ----------------
__global__ void k_hist(const int* __restrict__ rows, int nnz) {
    int i = blockIdx.x * blockDim.x + threadIdx.x;
    if (i < nnz) atomicAdd(&g_counts[rows[i]], 1);
}

// ---------------- Pass 3a: per-chunk exclusive scan ----------------
__global__ void k_scan_chunks(int n) {
    int b = blockIdx.x, t = threadIdx.x;
    int i = b * CHUNK + t;
    int v = (i < n) ? g_counts[i] : 0;
    int lane = t & 31, w = t >> 5;
    int x = v;
    #pragma unroll
    for (int d = 1; d < 32; d <<= 1) {
        int y = __shfl_up_sync(0xFFFFFFFFu, x, d);
        if (lane >= d) x += y;
    }
    __shared__ int wsum[32];
    if (lane == 31) wsum[w] = x;
    __syncthreads();
    if (w == 0) {
        int s = wsum[lane];
        #pragma unroll
        for (int d = 1; d < 32; d <<= 1) {
            int y = __shfl_up_sync(0xFFFFFFFFu, s, d);
            if (lane >= d) s += y;
        }
        wsum[lane] = s;
    }
    __syncthreads();
    int incl = x + (w > 0 ? wsum[w - 1] : 0);
    if (i < n) g_offsets[i] = incl - v;          // local exclusive
    if (t == CHUNK - 1) g_blocksums[b] = incl;   // chunk total
}

// ---------------- Pass 3b: scan chunk totals (1 block) ----------------
__global__ void k_scan_tops(int nb) {
    __shared__ int s[MAXBLK];
    int t = threadIdx.x;
    int own = (t < nb) ? g_blocksums[t] : 0;
    s[t] = own;
    __syncthreads();
    for (int d = 1; d < MAXBLK; d <<= 1) {
        int y = (t >= d) ? s[t - d] : 0;
        __syncthreads();
        s[t] += y;
        __syncthreads();
    }
    g_blockoff[t] = s[t] - own;   // exclusive
}

// ---------------- Pass 3c: add chunk bases, init cursor ----------------
__global__ void k_add_base(int n) {
    int i = blockIdx.x * blockDim.x + threadIdx.x;
    if (i < n) {
        int o = g_offsets[i] + g_blockoff[i / CHUNK];
        g_offsets[i] = o;
        g_cursor[i]  = o;
    }
}

// ---------------- Pass 4: scatter (col,val) by row ----------------
__global__ void k_scatter(const int* __restrict__ rows,
                          const int* __restrict__ cols,
                          const float* __restrict__ vals, int nnz) {
    int i = blockIdx.x * blockDim.x + threadIdx.x;
    if (i < nnz) {
        int r = rows[i];
        int p = atomicAdd(&g_cursor[r], 1);
        g_pairs[p] = make_float2(__int_as_float(cols[i]), vals[i]);
    }
}

// ---------------- Pass 5: warp-per-row gather SpMM ----------------
__global__ void __launch_bounds__(256)
k_spmm(const float* __restrict__ W, const float* __restrict__ bias,
       float* __restrict__ out, int n) {
    int gwarp = (blockIdx.x * blockDim.x + threadIdx.x) >> 5;
    int lane  = threadIdx.x & 31;
    if (gwarp >= n) return;
    int row   = gwarp;
    int start = g_offsets[row];
    int cnt   = g_counts[row];

    const float2* __restrict__ bias2 = (const float2*)bias;
    float2 acc = bias2[lane];   // lane owns output cols [2*lane, 2*lane+1]

    for (int base = 0; base < cnt; base += 32) {
        int k = base + lane;
        float2 p = (k < cnt) ? g_pairs[start + k] : make_float2(0.0f, 0.0f);
        int m = cnt - base; if (m > 32) m = 32;
        #pragma unroll 4
        for (int j = 0; j < m; ++j) {
            int   c = __shfl_sync(0xFFFFFFFFu, __float_as_int(p.x), j);
            float v = __shfl_sync(0xFFFFFFFFu, p.y, j);
            float2 w = *(const float2*)(W + (size_t)c * OUTF + 2 * lane);
            acc.x = fmaf(v, w.x, acc.x);
            acc.y = fmaf(v, w.y, acc.y);
        }
    }
    ((float2*)out)[(size_t)row * 32 + lane] = acc;
}

// ---------------- launch ----------------
extern "C" void kernel_launch(void* const* d_in, const int* in_sizes, int n_in,
                              void* d_out, int out_size) {
    const int*   index = (const int*)d_in[0];     // [2, nnz]
    const float* value = (const float*)d_in[1];   // [nnz]
    // d_in[2] = n (device scalar, unused; derive from out_size)
    const float* weight = (const float*)d_in[3];  // [in_f, 64]
    const float* bias   = (const float*)d_in[4];  // [64]
    float* out = (float*)d_out;

    int nnz = in_sizes[1];
    int n   = out_size / OUTF;

    const int* rows = index;
    const int* cols = index + nnz;

    int nb = (n + CHUNK - 1) / CHUNK;

    k_zero<<<(n + 255) / 256, 256>>>(n);
    k_hist<<<(nnz + 255) / 256, 256>>>(rows, nnz);
    k_scan_chunks<<<nb, CHUNK>>>(n);
    k_scan_tops<<<1, MAXBLK>>>(nb);
    k_add_base<<<(n + 255) / 256, 256>>>(n);
    k_scatter<<<(nnz + 255) / 256, 256>>>(rows, cols, value, nnz);

    int warps_per_block = 256 / 32;
    int blocks = (n + warps_per_block - 1) / warps_per_block;
    k_spmm<<<blocks, 256>>>(weight, bias, out, n);
}

// round 2
// speedup vs baseline: 1.0692x; 1.0692x over previous
#include <cuda_runtime.h>
#include <cuda_fp16.h>
#include <stdint.h>

// SparseLinear: out[n,64] = segment_sum(value * W[col,:], rows) + bias
// Pipeline: memset counts -> convert W to fp16 -> hist(+rank) ->
//           decoupled-lookback scan -> atomic-free scatter -> warp/row SpMM.

#define OUTF 64
#define N_MAX 100032
#define NNZ_MAX 4000000
#define CHUNK 1024
#define MAXBLK 256
#define INF_MAX 5120

__device__ int            g_counts[N_MAX];
__device__ int            g_offsets[N_MAX];
__device__ unsigned long long g_status[MAXBLK];   // (flag<<32)|value; 1=agg, 2=prefix
__device__ unsigned short g_rank[NNZ_MAX];
__device__ float2         g_pairs[NNZ_MAX];       // .x = col bits, .y = value
__device__ __half         g_wh[INF_MAX * OUTF];   // fp16 weight copy

// ---------------- convert W fp32 -> fp16 ----------------
__global__ void k_cvt(const float* __restrict__ W, int total) {
    int i = blockIdx.x * blockDim.x + threadIdx.x;
    if (i < total) g_wh[i] = __float2half_rn(W[i]);
}

// ---------------- histogram + per-element rank, zero scan status ----------------
__global__ void k_hist(const int* __restrict__ rows, int nnz, int nb) {
    int i = blockIdx.x * blockDim.x + threadIdx.x;
    if (i < nb) g_status[i] = 0ULL;
    if (i < nnz) {
        int r = rows[i];
        g_rank[i] = (unsigned short)atomicAdd(&g_counts[r], 1);
    }
}

// ---------------- single-pass exclusive scan (decoupled lookback) ----------------
__device__ __forceinline__ int warp_incl_scan(int x, int lane) {
    #pragma unroll
    for (int d = 1; d < 32; d <<= 1) {
        int y = __shfl_up_sync(0xFFFFFFFFu, x, d);
        if (lane >= d) x += y;
    }
    return x;
}

__global__ void __launch_bounds__(CHUNK) k_scan(int n) {
    int b = blockIdx.x, t = threadIdx.x;
    int lane = t & 31, w = t >> 5;
    int i = b * CHUNK + t;
    int v = (i < n) ? g_counts[i] : 0;

    int x = warp_incl_scan(v, lane);
    __shared__ int wsum[32];
    if (lane == 31) wsum[w] = x;
    __syncthreads();
    if (w == 0) wsum[lane] = warp_incl_scan(wsum[lane], lane);
    __syncthreads();
    int incl  = x + (w ? wsum[w - 1] : 0);
    int total = wsum[31];

    __shared__ int s_base;
    if (w == 0) {
        int base = 0;
        if (b == 0) {
            if (lane == 0)
                atomicExch(&g_status[0], (2ULL << 32) | (unsigned)total);
        } else {
            if (lane == 0)
                atomicExch(&g_status[b], (1ULL << 32) | (unsigned)total);
            int j = b - 1;
            while (true) {
                int idx = j - lane;
                unsigned flag; int val;
                if (idx >= 0) {
                    unsigned long long st;
                    do { st = atomicAdd(&g_status[idx], 0ULL); }
                    while ((st >> 32) == 0ULL);
                    flag = (unsigned)(st >> 32);
                    val  = (int)(unsigned)st;
                } else { flag = 2u; val = 0; }
                unsigned pmask = __ballot_sync(0xFFFFFFFFu, flag == 2u);
                if (pmask) {
                    int lead = __ffs(pmask) - 1;           // closest prefix to b
                    int c = (lane <= lead) ? val : 0;
                    #pragma unroll
                    for (int d = 16; d; d >>= 1) c += __shfl_down_sync(0xFFFFFFFFu, c, d);
                    base += __shfl_sync(0xFFFFFFFFu, c, 0);
                    break;
                } else {
                    int c = val;
                    #pragma unroll
                    for (int d = 16; d; d >>= 1) c += __shfl_down_sync(0xFFFFFFFFu, c, d);
                    base += __shfl_sync(0xFFFFFFFFu, c, 0);
                    j -= 32;
                }
            }
            if (lane == 0)
                atomicExch(&g_status[b], (2ULL << 32) | (unsigned)(total + base));
        }
        if (lane == 0) s_base = base;
    }
    __syncthreads();
    if (i < n) g_offsets[i] = s_base + incl - v;
}

// ---------------- atomic-free scatter ----------------
__global__ void k_scatter(const int* __restrict__ rows,
                          const int* __restrict__ cols,
                          const float* __restrict__ vals, int nnz) {
    int i = blockIdx.x * blockDim.x + threadIdx.x;
    if (i < nnz) {
        int r = rows[i];
        int p = g_offsets[r] + (int)g_rank[i];
        g_pairs[p] = make_float2(__int_as_float(cols[i]), vals[i]);
    }
}

// ---------------- warp-per-row gather SpMM (fp16 W, fp32 accumulate) ----------------
__global__ void __launch_bounds__(256)
k_spmm(const float* __restrict__ bias, float* __restrict__ out, int n) {
    int gwarp = (blockIdx.x * blockDim.x + threadIdx.x) >> 5;
    int lane  = threadIdx.x & 31;
    if (gwarp >= n) return;
    int start = g_offsets[gwarp];
    int cnt   = g_counts[gwarp];

    float2 acc = ((const float2*)bias)[lane];   // lane owns cols [2l, 2l+1]
    const __half2* __restrict__ wh2 = (const __half2*)g_wh;

    for (int base = 0; base < cnt; base += 32) {
        int k = base + lane;
        float2 p = (k < cnt) ? g_pairs[start + k] : make_float2(0.0f, 0.0f);
        int m = cnt - base; if (m > 32) m = 32;
        #pragma unroll 4
        for (int j = 0; j < m; ++j) {
            int   c = __shfl_sync(0xFFFFFFFFu, __float_as_int(p.x), j);
            float v = __shfl_sync(0xFFFFFFFFu, p.y, j);
            float2 wf = __half22float2(wh2[c * 32 + lane]);   // warp: 128B coalesced
            acc.x = fmaf(v, wf.x, acc.x);
            acc.y = fmaf(v, wf.y, acc.y);
        }
    }
    ((float2*)out)[(size_t)gwarp * 32 + lane] = acc;
}

// ---------------- launch ----------------
extern "C" void kernel_launch(void* const* d_in, const int* in_sizes, int n_in,
                              void* d_out, int out_size) {
    const int*   index  = (const int*)d_in[0];    // [2, nnz]
    const float* value  = (const float*)d_in[1];  // [nnz]
    const float* weight = (const float*)d_in[3];  // [in_f, 64]
    const float* bias   = (const float*)d_in[4];  // [64]
    float* out = (float*)d_out;

    int nnz  = in_sizes[1];
    int n    = out_size / OUTF;
    int wtot = in_sizes[3];

    const int* rows = index;
    const int* cols = index + nnz;
    int nb = (n + CHUNK - 1) / CHUNK;

    void* counts_ptr = nullptr;
    cudaGetSymbolAddress(&counts_ptr, g_counts);
    cudaMemsetAsync(counts_ptr, 0, (size_t)n * sizeof(int));

    k_cvt<<<(wtot + 255) / 256, 256>>>(weight, wtot);
    k_hist<<<(nnz + 255) / 256, 256>>>(rows, nnz, nb);
    k_scan<<<nb, CHUNK>>>(n);
    k_scatter<<<(nnz + 255) / 256, 256>>>(rows, cols, value, nnz);

    int blocks = (n * 32 + 255) / 256;
    k_spmm<<<blocks, 256>>>(bias, out, n);
}